// round 1
// baseline (speedup 1.0000x reference)
#include <cuda_runtime.h>
#include <math.h>

#define NFFT   8192
#define LSEQ   4095
#define DMODEL 768
#define NLAYERS 12
#define PHALF  2047
#define TWN    2048          // quarter-period twiddle table entries
#define SPAD   8704          // 8192 + 8192/16 padding
#define FFT_THREADS 512
#define SMEM_BYTES ((SPAD + TWN) * sizeof(float2))

// index padding: every 16th element skipped -> worst-case 2-way bank conflict
#define IDX(v) ((v) + ((v) >> 4))

// ---------------- device scratch ----------------
__device__ float  g_x[2 * DMODEL * LSEQ];                         // (B, D, L) 25 MB
__device__ float2 g_wspec[(size_t)NLAYERS * DMODEL * NFFT];       // 604 MB, perm-order, pre-conjugated

// ---------------- complex helpers ----------------
__device__ __forceinline__ float2 cmul(float2 a, float2 b) {
    return make_float2(fmaf(a.x, b.x, -a.y * b.y), fmaf(a.x, b.y, a.y * b.x));
}
__device__ __forceinline__ float2 cadd(float2 a, float2 b) { return make_float2(a.x + b.x, a.y + b.y); }
__device__ __forceinline__ float2 csub(float2 a, float2 b) { return make_float2(a.x - b.x, a.y - b.y); }

// reverse 6 base-4 digits of a 12-bit value
__device__ __forceinline__ int drev12(int x) {
    return ((x & 0x3) << 10) | ((x & 0xC) << 6) | ((x & 0x30) << 2)
         | ((x & 0xC0) >> 2) | ((x & 0x300) >> 6) | ((x & 0xC00) >> 10);
}

// e^{-2pi i k / 8192}, k in [0, 4096)
__device__ __forceinline__ float2 tw8192(const float2* TW, int k) {
    if (k < TWN) return TW[k];
    float2 t = TW[k - TWN];                 // multiply by -i
    return make_float2(t.y, -t.x);
}

__device__ __forceinline__ void build_table(float2* TW, int tid, int nt) {
    for (int k = tid; k < TWN; k += nt) {
        float s, c;
        sincospif(-(float)k / 4096.0f, &s, &c);   // angle = -2*pi*k/8192
        TW[k] = make_float2(c, s);
    }
}

// forward DIF: natural order in -> permuted order out
__device__ void fft_dif(float2* S, const float2* TW, int tid, int nt) {
    // radix-2 stage, Ncur = 8192
    for (int j = tid; j < 4096; j += nt) {
        float2 a = S[IDX(j)], b = S[IDX(j + 4096)];
        S[IDX(j)]        = cadd(a, b);
        S[IDX(j + 4096)] = cmul(csub(a, b), tw8192(TW, j));
    }
    __syncthreads();
    // radix-4 stages, Ncur = 4096 .. 4
    for (int ln = 12; ln >= 2; ln -= 2) {
        const int Q = 1 << (ln - 2);
        const int sh = 13 - ln;
        for (int bf = tid; bf < 2048; bf += nt) {
            int j    = bf & (Q - 1);
            int base = ((bf >> (ln - 2)) << ln) + j;
            float2 a0 = S[IDX(base)],         a1 = S[IDX(base + Q)];
            float2 a2 = S[IDX(base + 2 * Q)], a3 = S[IDX(base + 3 * Q)];
            float2 t0 = cadd(a0, a2), t1 = csub(a0, a2);
            float2 t2 = cadd(a1, a3), t3 = csub(a1, a3);
            float2 y0 = cadd(t0, t2);
            float2 y1 = make_float2(t1.x + t3.y, t1.y - t3.x);   // t1 - i t3
            float2 y2 = csub(t0, t2);
            float2 y3 = make_float2(t1.x - t3.y, t1.y + t3.x);   // t1 + i t3
            float2 w1 = TW[j << sh];
            float2 w2 = cmul(w1, w1);
            float2 w3 = cmul(w2, w1);
            S[IDX(base)]         = y0;
            S[IDX(base + Q)]     = cmul(y1, w1);
            S[IDX(base + 2 * Q)] = cmul(y2, w2);
            S[IDX(base + 3 * Q)] = cmul(y3, w3);
        }
        __syncthreads();
    }
}

// inverse DIT: permuted order in -> natural order out (unscaled; caller applies 1/N)
__device__ void ifft_dit(float2* S, const float2* TW, int tid, int nt) {
    for (int ln = 2; ln <= 12; ln += 2) {
        const int Q = 1 << (ln - 2);
        const int sh = 13 - ln;
        for (int bf = tid; bf < 2048; bf += nt) {
            int j    = bf & (Q - 1);
            int base = ((bf >> (ln - 2)) << ln) + j;
            float2 w1 = TW[j << sh]; w1.y = -w1.y;               // conj
            float2 w2 = cmul(w1, w1);
            float2 w3 = cmul(w2, w1);
            float2 a0 = S[IDX(base)];
            float2 a1 = cmul(S[IDX(base + Q)],     w1);
            float2 a2 = cmul(S[IDX(base + 2 * Q)], w2);
            float2 a3 = cmul(S[IDX(base + 3 * Q)], w3);
            float2 t0 = cadd(a0, a2), t1 = csub(a0, a2);
            float2 t2 = cadd(a1, a3), t3 = csub(a1, a3);
            S[IDX(base)]         = cadd(t0, t2);
            S[IDX(base + Q)]     = make_float2(t1.x - t3.y, t1.y + t3.x);  // t1 + i t3
            S[IDX(base + 2 * Q)] = csub(t0, t2);
            S[IDX(base + 3 * Q)] = make_float2(t1.x + t3.y, t1.y - t3.x);  // t1 - i t3
        }
        __syncthreads();
    }
    // final radix-2, Ncur = 8192
    for (int j = tid; j < 4096; j += nt) {
        float2 w = tw8192(TW, j); w.y = -w.y;                    // conj
        float2 a = S[IDX(j)];
        float2 b = cmul(S[IDX(j + 4096)], w);
        S[IDX(j)]        = cadd(a, b);
        S[IDX(j + 4096)] = csub(a, b);
    }
    __syncthreads();
}

// ---------------- kernel 1: embedding -> g_x (B, D, L) transposed ----------------
__global__ void __launch_bounds__(1024) embed_kernel(const int* __restrict__ ids,
                                                     const float* __restrict__ emb,
                                                     const float* __restrict__ pos) {
    __shared__ float tile[32][33];
    int b = blockIdx.z;
    int l = blockIdx.x * 32 + threadIdx.y;
    int d = blockIdx.y * 32 + threadIdx.x;
    float v = 0.0f;
    if (l < LSEQ) {
        int id = ids[b * LSEQ + l];
        v = emb[(size_t)id * DMODEL + d] + pos[(size_t)l * DMODEL + d];
    }
    tile[threadIdx.y][threadIdx.x] = v;
    __syncthreads();
    int l2 = blockIdx.x * 32 + threadIdx.x;
    int d2 = blockIdx.y * 32 + threadIdx.y;
    if (l2 < LSEQ)
        g_x[((size_t)b * DMODEL + d2) * LSEQ + l2] = tile[threadIdx.x][threadIdx.y];
}

// ---------------- kernel 2: all filter spectra, conj'd, perm-order ----------------
// one CTA per (layer, channel-pair): pack w[2d] + i*w[2d+1], FFT, unpack, store conj
__global__ void __launch_bounds__(FFT_THREADS) wspec_kernel(const float* __restrict__ filt_w) {
    extern __shared__ float2 sh[];
    float2* S  = sh;
    float2* TW = sh + SPAD;
    const int tid = threadIdx.x, nt = blockDim.x;
    const int layer = blockIdx.x / (DMODEL / 2);
    const int d0    = (blockIdx.x % (DMODEL / 2)) * 2;

    build_table(TW, tid, nt);
    const float* w0 = filt_w + ((size_t)layer * DMODEL + d0) * LSEQ;
    const float* w1 = w0 + LSEQ;
    for (int l = tid; l < NFFT; l += nt)
        S[IDX(l)] = (l < LSEQ) ? make_float2(w0[l], w1[l]) : make_float2(0.f, 0.f);
    __syncthreads();

    fft_dif(S, TW, tid, nt);

    float2* out0 = g_wspec + ((size_t)layer * DMODEL + d0) * NFFT;
    float2* out1 = out0 + NFFT;
    for (int jpos = tid; jpos < NFFT; jpos += nt) {
        int k  = (drev12(jpos & 4095) << 1) | (jpos >> 12);      // natural bin at this position
        int kn = (NFFT - k) & (NFFT - 1);
        int jn = ((kn & 1) << 12) | drev12(kn >> 1);             // position of bin N-k
        float2 Zk = S[IDX(jpos)];
        float2 Zn = S[IDX(jn)];
        // W0 = (Zk + conj Zn)/2 ; W1 = -i(Zk - conj Zn)/2 ; store conjugates
        out0[jpos] = make_float2(0.5f * (Zk.x + Zn.x), 0.5f * (Zn.y - Zk.y));
        out1[jpos] = make_float2(0.5f * (Zk.y + Zn.y), 0.5f * (Zk.x - Zn.x));
    }
}

// ---------------- kernel 3: one Hyena layer (FFT conv + residual + bias) ----------
// one CTA per channel d; batches packed as Re/Im
__global__ void __launch_bounds__(FFT_THREADS) conv_kernel(const float* __restrict__ filt_b,
                                                           int layer) {
    extern __shared__ float2 sh[];
    float2* S  = sh;
    float2* TW = sh + SPAD;
    const int tid = threadIdx.x, nt = blockDim.x;
    const int d = blockIdx.x;

    build_table(TW, tid, nt);
    float* x0 = g_x + (size_t)d * LSEQ;
    float* x1 = g_x + (size_t)(DMODEL + d) * LSEQ;
    for (int l = tid; l < NFFT; l += nt)
        S[IDX(l)] = (l < LSEQ) ? make_float2(x0[l], x1[l]) : make_float2(0.f, 0.f);
    __syncthreads();

    fft_dif(S, TW, tid, nt);

    const float2* wp = g_wspec + ((size_t)layer * DMODEL + d) * NFFT;
    for (int j = tid; j < NFFT; j += nt)
        S[IDX(j)] = cmul(S[IDX(j)], wp[j]);
    __syncthreads();

    ifft_dit(S, TW, tid, nt);

    const float bias = filt_b[layer * DMODEL + d];
    const float inv  = 1.0f / (float)NFFT;
    for (int t = tid; t < LSEQ; t += nt) {
        int s = (t - PHALF) & (NFFT - 1);
        float2 y = S[IDX(s)];
        x0[t] = x0[t] + y.x * inv + bias;
        x1[t] = x1[t] + y.y * inv + bias;
    }
}

// ---------------- kernel 4: LayerNorm + projection ----------------
__global__ void __launch_bounds__(1024) final_kernel(const float* __restrict__ ln_g,
                                                     const float* __restrict__ ln_b,
                                                     const float* __restrict__ qa_w,
                                                     const float* __restrict__ qa_b,
                                                     float* __restrict__ out) {
    __shared__ float red[8][32][32];
    const int b  = blockIdx.y;
    const int tx = threadIdx.x, ty = threadIdx.y;
    const int l  = blockIdx.x * 32 + tx;
    const bool valid = (l < LSEQ);

    float S = 0, S2 = 0, A0 = 0, A1 = 0, G0 = 0, G1 = 0, B0 = 0, B1 = 0;
    for (int d = ty; d < DMODEL; d += 32) {
        float v  = valid ? g_x[((size_t)b * DMODEL + d) * LSEQ + l] : 0.f;
        float g  = ln_g[d], bb = ln_b[d];
        float w0 = qa_w[2 * d], w1 = qa_w[2 * d + 1];
        S += v; S2 += v * v;
        float gv = g * v;
        A0 += gv * w0; A1 += gv * w1;
        G0 += g * w0;  G1 += g * w1;
        B0 += bb * w0; B1 += bb * w1;
    }
    red[0][ty][tx] = S;  red[1][ty][tx] = S2;
    red[2][ty][tx] = A0; red[3][ty][tx] = A1;
    red[4][ty][tx] = G0; red[5][ty][tx] = G1;
    red[6][ty][tx] = B0; red[7][ty][tx] = B1;
    __syncthreads();
    for (int s = 16; s > 0; s >>= 1) {
        if (ty < s) {
            #pragma unroll
            for (int a = 0; a < 8; a++) red[a][ty][tx] += red[a][ty + s][tx];
        }
        __syncthreads();
    }
    if (ty == 0 && valid) {
        float Sv = red[0][0][tx], S2v = red[1][0][tx];
        float a0 = red[2][0][tx], a1  = red[3][0][tx];
        float g0 = red[4][0][tx], g1  = red[5][0][tx];
        float b0 = red[6][0][tx], b1  = red[7][0][tx];
        float m   = Sv * (1.0f / DMODEL);
        float var = S2v * (1.0f / DMODEL) - m * m;
        float r   = rsqrtf(var + 1e-5f);
        float o0  = r * (a0 - m * g0) + b0 + qa_b[0];
        float o1  = r * (a1 - m * g1) + b1 + qa_b[1];
        out[b * LSEQ + l]            = o0;   // logits[...,0], shape (B,L)
        out[2 * LSEQ + b * LSEQ + l] = o1;   // logits[...,1] after B*L offset
    }
}

// ---------------- host launcher ----------------
extern "C" void kernel_launch(void* const* d_in, const int* in_sizes, int n_in,
                              void* d_out, int out_size) {
    const int*   ids  = (const int*)  d_in[0];
    const float* emb  = (const float*)d_in[1];
    const float* pos  = (const float*)d_in[2];
    const float* fw   = (const float*)d_in[3];
    const float* fb   = (const float*)d_in[4];
    const float* lng  = (const float*)d_in[5];
    const float* lnb  = (const float*)d_in[6];
    const float* qaw  = (const float*)d_in[7];
    const float* qab  = (const float*)d_in[8];
    float* out = (float*)d_out;

    cudaFuncSetAttribute(wspec_kernel, cudaFuncAttributeMaxDynamicSharedMemorySize, SMEM_BYTES);
    cudaFuncSetAttribute(conv_kernel,  cudaFuncAttributeMaxDynamicSharedMemorySize, SMEM_BYTES);

    embed_kernel<<<dim3(128, DMODEL / 32, 2), dim3(32, 32)>>>(ids, emb, pos);
    wspec_kernel<<<NLAYERS * (DMODEL / 2), FFT_THREADS, SMEM_BYTES>>>(fw);
    for (int i = 0; i < NLAYERS; i++)
        conv_kernel<<<DMODEL, FFT_THREADS, SMEM_BYTES>>>(fb, i);
    final_kernel<<<dim3(128, 2), dim3(32, 32)>>>(lng, lnb, qaw, qab, out);
}

// round 2
// speedup vs baseline: 2.1552x; 2.1552x over previous
#include <cuda_runtime.h>
#include <math.h>

#define NFFT    8192
#define LSEQ    4095
#define DMODEL  768
#define NLAYERS 12
#define TTHR    512
#define SPAD    8448                      // 8192 + 8192/32 padding
#define AP(p)   ((p) + ((p) >> 5))
#define SMEM_BYTES (SPAD * sizeof(float2))

// ---------------- device scratch ----------------
__device__ float2 g_x[DMODEL * LSEQ];                        // packed {batch0, batch1}, (D, L)
__device__ float2 g_wspec[(size_t)NLAYERS * DMODEL * NFFT];  // 604 MB, perm-order, pre-conjugated
__device__ float2 g_tw[512];                                 // W_8192^k, k in [0,512)

// ---------------- complex helpers ----------------
__device__ __forceinline__ float2 cadd(float2 a, float2 b) { return make_float2(a.x + b.x, a.y + b.y); }
__device__ __forceinline__ float2 csub(float2 a, float2 b) { return make_float2(a.x - b.x, a.y - b.y); }
__device__ __forceinline__ float2 cmul(float2 a, float2 b) {
    return make_float2(fmaf(a.x, b.x, -a.y * b.y), fmaf(a.x, b.y, a.y * b.x));
}
__device__ __forceinline__ float2 cmulf(float2 a, float c, float s) {
    return make_float2(fmaf(a.x, c, -a.y * s), fmaf(a.x, s, a.y * c));
}
__device__ __forceinline__ float2 conjf(float2 a) { return make_float2(a.x, -a.y); }

// 4-bit bit reversal (involution)
__device__ __forceinline__ constexpr int br4c(int r) {
    return ((r & 1) << 3) | ((r & 2) << 1) | ((r & 4) >> 1) | ((r & 8) >> 3);
}

// multiply by W16^k (forward) or conj (inverse); k compile-time after unroll
__device__ __forceinline__ float2 twk(float2 a, int k, bool cj) {
    const float c1 = 0.92387953251128675613f;
    const float s1 = 0.38268343236508977173f;
    const float r2 = 0.70710678118654752440f;
    float c, s;
    switch (k & 7) {
        case 0: return a;
        case 1: c =  c1; s = -s1; break;
        case 2: c =  r2; s = -r2; break;
        case 3: c =  s1; s = -c1; break;
        case 4: return cj ? make_float2(-a.y, a.x) : make_float2(a.y, -a.x);
        case 5: c = -s1; s = -c1; break;
        case 6: c = -r2; s = -r2; break;
        default: c = -c1; s = -s1; break;
    }
    if (cj) s = -s;
    return cmulf(a, c, s);
}

// forward DIF DFT16: natural input, slot q holds X[br4(q)]
__device__ __forceinline__ void dft16_dif(float2* v) {
    #pragma unroll
    for (int i = 0; i < 8; i++) {
        float2 a = v[i], b = v[i + 8];
        v[i] = cadd(a, b); v[i + 8] = twk(csub(a, b), i, false);
    }
    #pragma unroll
    for (int B = 0; B < 16; B += 8)
        #pragma unroll
        for (int i = 0; i < 4; i++) {
            float2 a = v[B + i], b = v[B + i + 4];
            v[B + i] = cadd(a, b); v[B + i + 4] = twk(csub(a, b), 2 * i, false);
        }
    #pragma unroll
    for (int B = 0; B < 16; B += 4)
        #pragma unroll
        for (int i = 0; i < 2; i++) {
            float2 a = v[B + i], b = v[B + i + 2];
            v[B + i] = cadd(a, b); v[B + i + 2] = twk(csub(a, b), 4 * i, false);
        }
    #pragma unroll
    for (int B = 0; B < 16; B += 2) {
        float2 a = v[B], b = v[B + 1];
        v[B] = cadd(a, b); v[B + 1] = csub(a, b);
    }
}

// inverse DIT DFT16 with conj twiddles: slot q holds X[br4(q)], natural output (unscaled)
__device__ __forceinline__ void dft16_dit_conj(float2* v) {
    #pragma unroll
    for (int B = 0; B < 16; B += 2) {
        float2 a = v[B], b = v[B + 1];
        v[B] = cadd(a, b); v[B + 1] = csub(a, b);
    }
    #pragma unroll
    for (int B = 0; B < 16; B += 4)
        #pragma unroll
        for (int i = 0; i < 2; i++) {
            float2 a = v[B + i], b = twk(v[B + i + 2], 4 * i, true);
            v[B + i] = cadd(a, b); v[B + i + 2] = csub(a, b);
        }
    #pragma unroll
    for (int B = 0; B < 16; B += 8)
        #pragma unroll
        for (int i = 0; i < 4; i++) {
            float2 a = v[B + i], b = twk(v[B + i + 4], 2 * i, true);
            v[B + i] = cadd(a, b); v[B + i + 4] = csub(a, b);
        }
    #pragma unroll
    for (int i = 0; i < 8; i++) {
        float2 a = v[i], b = twk(v[i + 8], i, true);
        v[i] = cadd(a, b); v[i + 8] = csub(a, b);
    }
}

// middle forward pass: 16-elem r/w at stride 2^SL from smem, anchor twiddle wa
template <int SL>
__device__ __forceinline__ void fwd_pass(float2* S, int base, float2 wa) {
    float2 v[16];
    #pragma unroll
    for (int j = 0; j < 16; j++) v[j] = S[AP(base + (j << SL))];
    dft16_dif(v);
    float2 acc = make_float2(1.f, 0.f);
    #pragma unroll
    for (int r = 0; r < 16; r++) {
        float2 val = v[br4c(r)];
        if (r) val = cmul(val, acc);
        S[AP(base + (r << SL))] = val;
        acc = cmul(acc, wa);
    }
}

// middle inverse pass (wac already conjugated)
template <int SL>
__device__ __forceinline__ void inv_pass(float2* S, int base, float2 wac) {
    float2 v[16];
    float2 acc = make_float2(1.f, 0.f);
    #pragma unroll
    for (int r = 0; r < 16; r++) {
        float2 val = S[AP(base + (r << SL))];
        if (r) val = cmul(val, acc);
        v[br4c(r)] = val;
        acc = cmul(acc, wac);
    }
    dft16_dit_conj(v);
    #pragma unroll
    for (int j = 0; j < 16; j++) S[AP(base + (j << SL))] = v[j];
}

// ---------------- kernel 0: twiddle table ----------------
__global__ void tw_init_kernel() {
    int k = threadIdx.x;   // 512 threads
    float s, c;
    sincospif(-(float)k / 4096.0f, &s, &c);   // angle = -2*pi*k/8192
    g_tw[k] = make_float2(c, s);
}

// ---------------- kernel 1: embedding -> g_x packed (D, L) ----------------
__global__ void __launch_bounds__(1024) embed_kernel(const int* __restrict__ ids,
                                                     const float* __restrict__ emb,
                                                     const float* __restrict__ pos) {
    __shared__ float t0[32][33], t1[32][33];
    int l = blockIdx.x * 32 + threadIdx.y;
    int d = blockIdx.y * 32 + threadIdx.x;
    float v0 = 0.f, v1 = 0.f;
    if (l < LSEQ) {
        int id0 = ids[l], id1 = ids[LSEQ + l];
        float p = pos[(size_t)l * DMODEL + d];
        v0 = emb[(size_t)id0 * DMODEL + d] + p;
        v1 = emb[(size_t)id1 * DMODEL + d] + p;
    }
    t0[threadIdx.y][threadIdx.x] = v0;
    t1[threadIdx.y][threadIdx.x] = v1;
    __syncthreads();
    int l2 = blockIdx.x * 32 + threadIdx.x;
    int d2 = blockIdx.y * 32 + threadIdx.y;
    if (l2 < LSEQ)
        g_x[(size_t)d2 * LSEQ + l2] = make_float2(t0[threadIdx.x][threadIdx.y],
                                                  t1[threadIdx.x][threadIdx.y]);
}

// ---------------- kernel 2: filter spectra (perm-order, pre-conjugated) ----------------
__global__ void __launch_bounds__(TTHR, 2) wspec_kernel(const float* __restrict__ filt_w) {
    extern __shared__ float2 S[];
    const int t = threadIdx.x;
    const int layer = blockIdx.x / (DMODEL / 2);
    const int d0 = (blockIdx.x % (DMODEL / 2)) * 2;
    const float* w0 = filt_w + ((size_t)layer * DMODEL + d0) * LSEQ;
    const float* w1 = w0 + LSEQ;

    // pass A: global -> regs -> smem
    {
        float2 v[16];
        #pragma unroll
        for (int j = 0; j < 16; j++) {
            int n = (j << 9) + t;
            v[j] = (n < LSEQ) ? make_float2(w0[n], w1[n]) : make_float2(0.f, 0.f);
        }
        dft16_dif(v);
        float2 wa = g_tw[t];
        float2 acc = make_float2(1.f, 0.f);
        #pragma unroll
        for (int r = 0; r < 16; r++) {
            float2 val = v[br4c(r)];
            if (r) val = cmul(val, acc);
            S[AP((r << 9) + t)] = val;
            acc = cmul(acc, wa);
        }
    }
    __syncthreads();
    const int ra = t >> 5, vv = t & 31;
    fwd_pass<5>(S, (ra << 9) + vv, g_tw[vv << 4]);
    __syncthreads();
    const int rb = (t >> 1) & 15, w = t & 1;
    fwd_pass<1>(S, (ra << 9) + (rb << 5) + w, w ? g_tw[256] : make_float2(1.f, 0.f));
    __syncthreads();
    // final radix-2 (adjacent pairs)
    #pragma unroll
    for (int i = 0; i < 8; i++) {
        int p = (t << 4) + 2 * i;
        float2 a = S[AP(p)], b = S[AP(p + 1)];
        S[AP(p)] = cadd(a, b); S[AP(p + 1)] = csub(a, b);
    }
    __syncthreads();
    // unpack packed-real spectra, store conjugates in perm order
    float2* out0 = g_wspec + ((size_t)layer * DMODEL + d0) * NFFT;
    float2* out1 = out0 + NFFT;
    #pragma unroll
    for (int it = 0; it < 16; it++) {
        int p = t + (it << 9);
        int pra = p >> 9, prb = (p >> 5) & 15, prc = (p >> 1) & 15, psd = p & 1;
        int k = pra | (prb << 4) | (prc << 8) | (psd << 12);
        int kn = (NFFT - k) & (NFFT - 1);
        int pn = ((kn & 15) << 9) | (((kn >> 4) & 15) << 5) | (((kn >> 8) & 15) << 1) | (kn >> 12);
        float2 Zk = S[AP(p)], Zn = S[AP(pn)];
        out0[p] = make_float2(0.5f * (Zk.x + Zn.x), 0.5f * (Zn.y - Zk.y));
        out1[p] = make_float2(0.5f * (Zk.y + Zn.y), 0.5f * (Zk.x - Zn.x));
    }
}

// ---------------- kernel 3: one Hyena layer (register FFT conv) ----------------
__global__ void __launch_bounds__(TTHR, 2) conv_kernel(const float* __restrict__ filt_b,
                                                       int layer) {
    extern __shared__ float2 S[];
    const int t = threadIdx.x;
    const int d = blockIdx.x;
    float2* xrow = g_x + (size_t)d * LSEQ;

    // pass A: global -> regs -> smem
    {
        float2 v[16];
        #pragma unroll
        for (int j = 0; j < 16; j++) {
            int n = (j << 9) + t;
            v[j] = (n < LSEQ) ? xrow[n] : make_float2(0.f, 0.f);
        }
        dft16_dif(v);
        float2 wa = g_tw[t];
        float2 acc = make_float2(1.f, 0.f);
        #pragma unroll
        for (int r = 0; r < 16; r++) {
            float2 val = v[br4c(r)];
            if (r) val = cmul(val, acc);
            S[AP((r << 9) + t)] = val;
            acc = cmul(acc, wa);
        }
    }
    __syncthreads();
    const int ra = t >> 5, vv = t & 31;
    const int baseB = (ra << 9) + vv;
    fwd_pass<5>(S, baseB, g_tw[vv << 4]);
    __syncthreads();
    const int rb = (t >> 1) & 15, w = t & 1;
    const int baseC = (ra << 9) + (rb << 5) + w;
    fwd_pass<1>(S, baseC, w ? g_tw[256] : make_float2(1.f, 0.f));
    __syncthreads();
    // pass D: radix-2 fwd + spectrum multiply + radix-2 inv (all in regs)
    {
        const float4* wp = (const float4*)(g_wspec + ((size_t)layer * DMODEL + d) * NFFT + ((size_t)t << 4));
        #pragma unroll
        for (int i = 0; i < 8; i++) {
            int p = (t << 4) + 2 * i;
            float2 a = S[AP(p)], b = S[AP(p + 1)];
            float4 W = wp[i];
            float2 e = cmul(cadd(a, b), make_float2(W.x, W.y));
            float2 o = cmul(csub(a, b), make_float2(W.z, W.w));
            S[AP(p)]     = cadd(e, o);
            S[AP(p + 1)] = csub(e, o);
        }
    }
    __syncthreads();
    inv_pass<1>(S, baseC, w ? conjf(g_tw[256]) : make_float2(1.f, 0.f));
    __syncthreads();
    inv_pass<5>(S, baseB, conjf(g_tw[vv << 4]));
    __syncthreads();
    // pass A': smem -> regs -> global with residual + bias
    {
        float2 v[16];
        float2 wac = conjf(g_tw[t]);
        float2 acc = make_float2(1.f, 0.f);
        #pragma unroll
        for (int r = 0; r < 16; r++) {
            float2 val = S[AP((r << 9) + t)];
            if (r) val = cmul(val, acc);
            v[br4c(r)] = val;
            acc = cmul(acc, wac);
        }
        dft16_dit_conj(v);
        const float bias = filt_b[layer * DMODEL + d];
        const float inv = 1.0f / (float)NFFT;
        #pragma unroll
        for (int j = 0; j < 16; j++) {
            int n = (j << 9) + t;
            int to = (n + 2047) & (NFFT - 1);
            if (to < LSEQ) {
                float2 old = xrow[to];
                xrow[to] = make_float2(old.x + v[j].x * inv + bias,
                                       old.y + v[j].y * inv + bias);
            }
        }
    }
}

// ---------------- kernel 4: LayerNorm + projection ----------------
__global__ void __launch_bounds__(1024) final_kernel(const float* __restrict__ ln_g,
                                                     const float* __restrict__ ln_b,
                                                     const float* __restrict__ qa_w,
                                                     const float* __restrict__ qa_b,
                                                     float* __restrict__ out) {
    __shared__ float red[8][32][32];
    const int b  = blockIdx.y;
    const int tx = threadIdx.x, ty = threadIdx.y;
    const int l  = blockIdx.x * 32 + tx;
    const bool valid = (l < LSEQ);

    float S = 0, S2 = 0, A0 = 0, A1 = 0, G0 = 0, G1 = 0, B0 = 0, B1 = 0;
    for (int d = ty; d < DMODEL; d += 32) {
        float2 xv = valid ? g_x[(size_t)d * LSEQ + l] : make_float2(0.f, 0.f);
        float v  = b ? xv.y : xv.x;
        float g  = ln_g[d], bb = ln_b[d];
        float w0 = qa_w[2 * d], w1 = qa_w[2 * d + 1];
        S += v; S2 += v * v;
        float gv = g * v;
        A0 += gv * w0; A1 += gv * w1;
        G0 += g * w0;  G1 += g * w1;
        B0 += bb * w0; B1 += bb * w1;
    }
    red[0][ty][tx] = S;  red[1][ty][tx] = S2;
    red[2][ty][tx] = A0; red[3][ty][tx] = A1;
    red[4][ty][tx] = G0; red[5][ty][tx] = G1;
    red[6][ty][tx] = B0; red[7][ty][tx] = B1;
    __syncthreads();
    for (int s = 16; s > 0; s >>= 1) {
        if (ty < s) {
            #pragma unroll
            for (int a = 0; a < 8; a++) red[a][ty][tx] += red[a][ty + s][tx];
        }
        __syncthreads();
    }
    if (ty == 0 && valid) {
        float Sv = red[0][0][tx], S2v = red[1][0][tx];
        float a0 = red[2][0][tx], a1  = red[3][0][tx];
        float g0 = red[4][0][tx], g1  = red[5][0][tx];
        float b0 = red[6][0][tx], b1  = red[7][0][tx];
        float m   = Sv * (1.0f / DMODEL);
        float var = S2v * (1.0f / DMODEL) - m * m;
        float r   = rsqrtf(var + 1e-5f);
        float o0  = r * (a0 - m * g0) + b0 + qa_b[0];
        float o1  = r * (a1 - m * g1) + b1 + qa_b[1];
        out[b * LSEQ + l]            = o0;
        out[2 * LSEQ + b * LSEQ + l] = o1;
    }
}

// ---------------- host launcher ----------------
extern "C" void kernel_launch(void* const* d_in, const int* in_sizes, int n_in,
                              void* d_out, int out_size) {
    const int*   ids  = (const int*)  d_in[0];
    const float* emb  = (const float*)d_in[1];
    const float* pos  = (const float*)d_in[2];
    const float* fw   = (const float*)d_in[3];
    const float* fb   = (const float*)d_in[4];
    const float* lng  = (const float*)d_in[5];
    const float* lnb  = (const float*)d_in[6];
    const float* qaw  = (const float*)d_in[7];
    const float* qab  = (const float*)d_in[8];
    float* out = (float*)d_out;

    cudaFuncSetAttribute(wspec_kernel, cudaFuncAttributeMaxDynamicSharedMemorySize, SMEM_BYTES);
    cudaFuncSetAttribute(conv_kernel,  cudaFuncAttributeMaxDynamicSharedMemorySize, SMEM_BYTES);

    tw_init_kernel<<<1, 512>>>();
    embed_kernel<<<dim3(128, DMODEL / 32), dim3(32, 32)>>>(ids, emb, pos);
    wspec_kernel<<<NLAYERS * (DMODEL / 2), TTHR, SMEM_BYTES>>>(fw);
    for (int i = 0; i < NLAYERS; i++)
        conv_kernel<<<DMODEL, TTHR, SMEM_BYTES>>>(fb, i);
    final_kernel<<<dim3(128, 2), dim3(32, 32)>>>(lng, lnb, qaw, qab, out);
}